// round 1
// baseline (speedup 1.0000x reference)
#include <cuda_runtime.h>
#include <math.h>

// ---------------- problem constants ----------------
#define Bsz 8192
#define Dd  1024
#define Uu  512
#define Ff  4
#define Ee  4
#define Tt  2
#define Gg  5   // F+1 experts for gating

// ---------------- scratch (static device arrays; no allocation allowed) ----
__device__ float g_common[Bsz * Uu];          // 16 MB
__device__ float g_field [Bsz * Ff * Uu];     // 64 MB
__device__ float g_mask  [Bsz * Ff * Ee];     // 512 KB

// ---------------- GEMM tiling ----------------
#define BM 128
#define BN 128
#define BK 8
#define TM 8
#define TN 8
#define NTHREADS 256

// ============================================================
// Kernel 0: field/expert activation masks
// fields 0,1 (discrete): expert e active iff x[b, f*4+e] > 0
// fields 2,3 (continuous): bucket x[b, 8+(f-2)] by {-0.5, 0, 0.5}
// ============================================================
__global__ void mask_kernel(const float* __restrict__ x)
{
    int b = blockIdx.x * blockDim.x + threadIdx.x;
    if (b >= Bsz) return;
    const float* xr = x + (size_t)b * Dd;
    float* mr = g_mask + (size_t)b * (Ff * Ee);
#pragma unroll
    for (int f = 0; f < 2; f++)
#pragma unroll
        for (int e = 0; e < 4; e++)
            mr[f * Ee + e] = (xr[f * 4 + e] > 0.f) ? 1.f : 0.f;
#pragma unroll
    for (int f = 2; f < 4; f++) {
        float v = xr[8 + (f - 2)];
        mr[f * Ee + 0] = (v > -1e10f && v <= -0.5f) ? 1.f : 0.f;
        mr[f * Ee + 1] = (v > -0.5f  && v <=  0.0f) ? 1.f : 0.f;
        mr[f * Ee + 2] = (v >  0.0f  && v <=  0.5f) ? 1.f : 0.f;
        mr[f * Ee + 3] = (v >  0.5f  && v <=  1e10f) ? 1.f : 0.f;
    }
}

// ============================================================
// Kernel 1: common expert  g_common = relu(x @ Wc + bc)
// 128x128x8 double-buffered SMEM GEMM, 8x8 per thread.
// ============================================================
__global__ __launch_bounds__(NTHREADS) void gemm_common_kernel(
    const float* __restrict__ x, const float* __restrict__ Wc,
    const float* __restrict__ bc)
{
    __shared__ float As[2][BK][BM];
    __shared__ float Bs[2][BK][BN];

    const int tid  = threadIdx.x;
    const int bm0  = blockIdx.x * BM;
    const int bn0  = blockIdx.y * BN;
    const int arow = tid >> 1;
    const int acol = (tid & 1) * 4;
    const int brow = tid >> 5;
    const int bcol = (tid & 31) * 4;
    const int ty   = tid >> 4, tx = tid & 15;
    const int tm0  = ty * TM, tn0 = tx * TN;

    const float* xA = x  + (size_t)(bm0 + arow) * Dd + acol;
    const float* WB = Wc + (size_t)brow * Uu + bn0 + bcol;

    float acc[TM][TN] = {};

    float4 a4 = *(const float4*)xA;
    float4 b4 = *(const float4*)WB;
    As[0][acol + 0][arow] = a4.x; As[0][acol + 1][arow] = a4.y;
    As[0][acol + 2][arow] = a4.z; As[0][acol + 3][arow] = a4.w;
    *(float4*)&Bs[0][brow][bcol] = b4;
    __syncthreads();

    const int ntiles = Dd / BK;
    int buf = 0;
    for (int t = 0; t < ntiles; t++) {
        if (t + 1 < ntiles) {
            a4 = *(const float4*)(xA + (t + 1) * BK);
            b4 = *(const float4*)(WB + (size_t)(t + 1) * BK * Uu);
        }
#pragma unroll
        for (int k = 0; k < BK; k++) {
            float af[TM], bf[TN];
#pragma unroll
            for (int i = 0; i < TM; i++) af[i] = As[buf][k][tm0 + i];
#pragma unroll
            for (int j = 0; j < TN; j++) bf[j] = Bs[buf][k][tn0 + j];
#pragma unroll
            for (int i = 0; i < TM; i++)
#pragma unroll
                for (int j = 0; j < TN; j++)
                    acc[i][j] = fmaf(af[i], bf[j], acc[i][j]);
        }
        if (t + 1 < ntiles) {
            int nb = buf ^ 1;
            As[nb][acol + 0][arow] = a4.x; As[nb][acol + 1][arow] = a4.y;
            As[nb][acol + 2][arow] = a4.z; As[nb][acol + 3][arow] = a4.w;
            *(float4*)&Bs[nb][brow][bcol] = b4;
        }
        __syncthreads();
        buf ^= 1;
    }

#pragma unroll
    for (int i = 0; i < TM; i++) {
        size_t row = (size_t)(bm0 + tm0 + i) * Uu + bn0 + tn0;
#pragma unroll
        for (int j = 0; j < TN; j++) {
            float v = acc[i][j] + bc[bn0 + tn0 + j];
            g_common[row + j] = v > 0.f ? v : 0.f;
        }
    }
}

// ============================================================
// Kernel 2: field experts.
// For each (b-tile, u-tile, f): loop e = 0..3, GEMM against We[f][e],
// epilogue bias+relu, multiply by mask[b,f,e], accumulate into g_field.
// Per-thread gmem accumulate (no atomics, no double register acc).
// ============================================================
__global__ __launch_bounds__(NTHREADS) void gemm_field_kernel(
    const float* __restrict__ x, const float* __restrict__ We,
    const float* __restrict__ be)
{
    __shared__ float As[2][BK][BM];
    __shared__ float Bs[2][BK][BN];
    __shared__ float msk[Ee][BM];

    const int tid  = threadIdx.x;
    const int bm0  = blockIdx.x * BM;
    const int bn0  = blockIdx.y * BN;
    const int f    = blockIdx.z;
    const int arow = tid >> 1;
    const int acol = (tid & 1) * 4;
    const int brow = tid >> 5;
    const int bcol = (tid & 31) * 4;
    const int ty   = tid >> 4, tx = tid & 15;
    const int tm0  = ty * TM, tn0 = tx * TN;

    const float* xA = x + (size_t)(bm0 + arow) * Dd + acol;

    // load masks for this tile's 128 rows, all E experts
    for (int i = tid; i < Ee * BM; i += NTHREADS) {
        int e = i / BM, m = i - e * BM;
        msk[e][m] = g_mask[(size_t)(bm0 + m) * (Ff * Ee) + f * Ee + e];
    }

    const int ntiles = Dd / BK;

    for (int e = 0; e < Ee; e++) {
        const float* W  = We + (size_t)(f * Ee + e) * Dd * Uu;
        const float* WB = W + (size_t)brow * Uu + bn0 + bcol;

        float acc[TM][TN] = {};

        float4 a4 = *(const float4*)xA;
        float4 b4 = *(const float4*)WB;
        As[0][acol + 0][arow] = a4.x; As[0][acol + 1][arow] = a4.y;
        As[0][acol + 2][arow] = a4.z; As[0][acol + 3][arow] = a4.w;
        *(float4*)&Bs[0][brow][bcol] = b4;
        __syncthreads();   // also covers msk stores on e==0

        int buf = 0;
        for (int t = 0; t < ntiles; t++) {
            if (t + 1 < ntiles) {
                a4 = *(const float4*)(xA + (t + 1) * BK);
                b4 = *(const float4*)(WB + (size_t)(t + 1) * BK * Uu);
            }
#pragma unroll
            for (int k = 0; k < BK; k++) {
                float af[TM], bf[TN];
#pragma unroll
                for (int i = 0; i < TM; i++) af[i] = As[buf][k][tm0 + i];
#pragma unroll
                for (int j = 0; j < TN; j++) bf[j] = Bs[buf][k][tn0 + j];
#pragma unroll
                for (int i = 0; i < TM; i++)
#pragma unroll
                    for (int j = 0; j < TN; j++)
                        acc[i][j] = fmaf(af[i], bf[j], acc[i][j]);
            }
            if (t + 1 < ntiles) {
                int nb = buf ^ 1;
                As[nb][acol + 0][arow] = a4.x; As[nb][acol + 1][arow] = a4.y;
                As[nb][acol + 2][arow] = a4.z; As[nb][acol + 3][arow] = a4.w;
                *(float4*)&Bs[nb][brow][bcol] = b4;
            }
            __syncthreads();
            buf ^= 1;
        }

        // epilogue: bias + relu + mask, accumulate into g_field
        const float* bep = be + (size_t)(f * Ee + e) * Uu + bn0 + tn0;
#pragma unroll
        for (int i = 0; i < TM; i++) {
            float m = msk[e][tm0 + i];
            size_t row = (size_t)(bm0 + tm0 + i) * (Ff * Uu) + (size_t)f * Uu + bn0 + tn0;
#pragma unroll
            for (int j = 0; j < TN; j++) {
                float v = acc[i][j] + bep[j];
                v = v > 0.f ? v : 0.f;
                v *= m;
                if (e == 0) g_field[row + j] = v;
                else        g_field[row + j] += v;
            }
        }
    }
}

// ============================================================
// Kernel 3: fused per-row epilogue.
// One block per batch row b (320 threads = 10 warps):
//   - att/upd sigmoid dots over cat([common, field], 2U)   (warps 0..7)
//   - gate logits x . Wg[t,:,g]                            (warps 0..9)
//   - softmax over F+1, field_final blend, task mix, write out [T,U]
// ============================================================
__global__ __launch_bounds__(320) void epilogue_kernel(
    const float* __restrict__ x,
    const float* __restrict__ Wg, const float* __restrict__ bg,
    const float* __restrict__ Wa, const float* __restrict__ ba,
    const float* __restrict__ Wu, const float* __restrict__ bu,
    float* __restrict__ out)
{
    const int b = blockIdx.x;
    __shared__ float xs[Dd];
    __shared__ float cs[Uu];
    __shared__ float fs[Ff][Uu];
    __shared__ float s_att[Ff], s_upd[Ff];
    __shared__ float s_logit[Tt][Gg];
    __shared__ float s_gates[Tt][Gg];

    const int tid = threadIdx.x;
    for (int i = tid; i < Dd; i += 320) xs[i] = x[(size_t)b * Dd + i];
    for (int i = tid; i < Uu; i += 320) cs[i] = g_common[(size_t)b * Uu + i];
    for (int i = tid; i < Ff * Uu; i += 320) fs[0][i] = g_field[(size_t)b * Ff * Uu + i];
    __syncthreads();

    const int w = tid >> 5, lane = tid & 31;

    // attention / update dots: warp w<8 handles (f = w>>1, a/u = w&1)
    if (w < 8) {
        int f = w >> 1;
        const float* Wv = (w & 1) ? (Wu + (size_t)f * 2 * Uu) : (Wa + (size_t)f * 2 * Uu);
        float s = 0.f;
        for (int k = lane; k < Uu; k += 32) s = fmaf(cs[k],    Wv[k],      s);
        for (int k = lane; k < Uu; k += 32) s = fmaf(fs[f][k], Wv[Uu + k], s);
#pragma unroll
        for (int o = 16; o; o >>= 1) s += __shfl_xor_sync(0xffffffffu, s, o);
        if (lane == 0) {
            float bias = (w & 1) ? bu[f] : ba[f];
            float v = 1.f / (1.f + expf(-(s + bias)));
            if (w & 1) s_upd[f] = v; else s_att[f] = v;
        }
    }

    // gate logits: warp w = t*5 + g
    {
        int t = w / Gg, g = w - t * Gg;
        float s = 0.f;
        for (int d = lane; d < Dd; d += 32)
            s = fmaf(xs[d], Wg[((size_t)t * Dd + d) * Gg + g], s);
#pragma unroll
        for (int o = 16; o; o >>= 1) s += __shfl_xor_sync(0xffffffffu, s, o);
        if (lane == 0) s_logit[t][g] = s + bg[t * Gg + g];
    }
    __syncthreads();

    // softmax over F+1 experts per task
    if (tid < Tt) {
        float mx = s_logit[tid][0];
#pragma unroll
        for (int g = 1; g < Gg; g++) mx = fmaxf(mx, s_logit[tid][g]);
        float ex[Gg], sum = 0.f;
#pragma unroll
        for (int g = 0; g < Gg; g++) { ex[g] = expf(s_logit[tid][g] - mx); sum += ex[g]; }
        float inv = 1.f / sum;
#pragma unroll
        for (int g = 0; g < Gg; g++) s_gates[tid][g] = ex[g] * inv;
    }
    __syncthreads();

    // field_final blend + task mixing, write out [T, U]
    for (int u = tid; u < Uu; u += 320) {
        float c = cs[u];
        float ffv[Ff];
#pragma unroll
        for (int f = 0; f < Ff; f++) {
            float fo = fs[f][u];
            float fa = s_att[f] * fo;
            ffv[f] = s_upd[f] * fa + (1.f - s_upd[f]) * c;
        }
#pragma unroll
        for (int t = 0; t < Tt; t++) {
            float o = s_gates[t][0] * c;
#pragma unroll
            for (int f = 0; f < Ff; f++) o = fmaf(s_gates[t][1 + f], ffv[f], o);
            out[((size_t)b * Tt + t) * Uu + u] = o;
        }
    }
}

// ============================================================
// launch
// ============================================================
extern "C" void kernel_launch(void* const* d_in, const int* in_sizes, int n_in,
                              void* d_out, int out_size)
{
    const float* x  = (const float*)d_in[0];
    const float* Wc = (const float*)d_in[1];
    const float* bc = (const float*)d_in[2];
    const float* We = (const float*)d_in[3];
    const float* be = (const float*)d_in[4];
    const float* Wg = (const float*)d_in[5];
    const float* bg = (const float*)d_in[6];
    const float* Wa = (const float*)d_in[7];
    const float* ba = (const float*)d_in[8];
    const float* Wu = (const float*)d_in[9];
    const float* bu = (const float*)d_in[10];
    float* out = (float*)d_out;

    mask_kernel<<<Bsz / 256, 256>>>(x);
    gemm_common_kernel<<<dim3(Bsz / BM, Uu / BN), NTHREADS>>>(x, Wc, bc);
    gemm_field_kernel<<<dim3(Bsz / BM, Uu / BN, Ff), NTHREADS>>>(x, We, be);
    epilogue_kernel<<<Bsz, 320>>>(x, Wg, bg, Wa, ba, Wu, bu, out);
}

// round 5
// speedup vs baseline: 2.5147x; 2.5147x over previous
#include <cuda_runtime.h>
#include <cuda_bf16.h>
#include <math.h>
#include <stdint.h>

// ---------------- problem constants ----------------
#define Bsz 8192
#define Dd  1024
#define Uu  512
#define Ff  4
#define Ee  4
#define Tt  2
#define Gg  5
#define NEXP 17

// ---------------- scratch ----------------
__device__ float g_common[Bsz * Uu];
__device__ float g_field [Bsz * Ff * Uu];
__device__ float g_mask  [Bsz * Ff * Ee];
__device__ __nv_bfloat16 g_xhi[Bsz * Dd];
__device__ __nv_bfloat16 g_xlo[Bsz * Dd];
__device__ __nv_bfloat16 g_whi[(size_t)NEXP * Uu * Dd];   // [ez][u][d]
__device__ __nv_bfloat16 g_wlo[(size_t)NEXP * Uu * Dd];

// ---------------- GEMM config ----------------
#define BM 128
#define BN 256
#define BK 64
#define AHI 0
#define ALO 16384
#define BHI 32768
#define BLO 65536
#define STAGE 98304
#define MSK_OFF (2 * STAGE)
#define DSM_TOTAL (2 * STAGE + 2048 + 32)

#define SWZ(o) ((o) ^ (((o) >> 3) & 0x70))

__device__ __forceinline__ uint32_t s2u(const void* p) {
    return (uint32_t)__cvta_generic_to_shared(p);
}

__device__ __forceinline__ void cpa16(uint32_t dst, const void* src) {
    asm volatile("cp.async.cg.shared.global [%0], [%1], 16;"
                 :: "r"(dst), "l"(__cvta_generic_to_global(src)));
}
#define CP_COMMIT() asm volatile("cp.async.commit_group;" ::: "memory")
#define CP_WAIT(n)  asm volatile("cp.async.wait_group %0;" :: "n"(n) : "memory")

__device__ __forceinline__ void ldsm4(uint32_t* r, uint32_t addr) {
    asm volatile("ldmatrix.sync.aligned.m8n8.x4.shared.b16 {%0,%1,%2,%3}, [%4];"
                 : "=r"(r[0]), "=r"(r[1]), "=r"(r[2]), "=r"(r[3]) : "r"(addr));
}

__device__ __forceinline__ void mma16816(float* c, const uint32_t* a, uint32_t b0, uint32_t b1) {
    asm volatile(
        "mma.sync.aligned.m16n8k16.row.col.f32.bf16.bf16.f32 "
        "{%0,%1,%2,%3}, {%4,%5,%6,%7}, {%8,%9}, {%0,%1,%2,%3};"
        : "+f"(c[0]), "+f"(c[1]), "+f"(c[2]), "+f"(c[3])
        : "r"(a[0]), "r"(a[1]), "r"(a[2]), "r"(a[3]), "r"(b0), "r"(b1));
}

// issue one k-chunk's cp.async loads into stage buf (A always reloaded —
// stage buffers do NOT retain per-chunk A across the expert loop)
__device__ __forceinline__ void issue_chunk(uint32_t sb, int buf, int ch,
                                            const __nv_bfloat16* __restrict__ wbh,
                                            const __nv_bfloat16* __restrict__ wbl,
                                            int m0, int n0, int tid)
{
    uint32_t st = sb + (uint32_t)buf * STAGE;
#pragma unroll
    for (int i = 0; i < 4; i++) {
        int u = tid + i * 256, r = u >> 3, cc = u & 7;
        size_t go = (size_t)(m0 + r) * Dd + ch * 64 + cc * 8;
        uint32_t so = SWZ(r * 128 + cc * 16);
        cpa16(st + AHI + so, g_xhi + go);
        cpa16(st + ALO + so, g_xlo + go);
    }
#pragma unroll
    for (int i = 0; i < 8; i++) {
        int u = tid + i * 256, r = u >> 3, cc = u & 7;
        size_t go = (size_t)(n0 + r) * Dd + ch * 64 + cc * 8;
        uint32_t so = SWZ(r * 128 + cc * 16);
        cpa16(st + BHI + so, wbh + go);
        cpa16(st + BLO + so, wbl + go);
    }
    CP_COMMIT();
}

// ============================================================
// prep kernels
// ============================================================
__global__ void mask_kernel(const float* __restrict__ x)
{
    int b = blockIdx.x * blockDim.x + threadIdx.x;
    if (b >= Bsz) return;
    const float* xr = x + (size_t)b * Dd;
    float* mr = g_mask + (size_t)b * (Ff * Ee);
#pragma unroll
    for (int f = 0; f < 2; f++)
#pragma unroll
        for (int e = 0; e < 4; e++)
            mr[f * Ee + e] = (xr[f * 4 + e] > 0.f) ? 1.f : 0.f;
#pragma unroll
    for (int f = 2; f < 4; f++) {
        float v = xr[8 + (f - 2)];
        mr[f * Ee + 0] = (v > -1e10f && v <= -0.5f) ? 1.f : 0.f;
        mr[f * Ee + 1] = (v > -0.5f  && v <=  0.0f) ? 1.f : 0.f;
        mr[f * Ee + 2] = (v >  0.0f  && v <=  0.5f) ? 1.f : 0.f;
        mr[f * Ee + 3] = (v >  0.5f  && v <=  1e10f) ? 1.f : 0.f;
    }
}

__global__ void splitx_kernel(const float* __restrict__ x)
{
    int i = blockIdx.x * blockDim.x + threadIdx.x;
    float4 v = ((const float4*)x)[i];
    int o = i * 4;
    float vv[4] = {v.x, v.y, v.z, v.w};
#pragma unroll
    for (int k = 0; k < 4; k++) {
        __nv_bfloat16 hi = __float2bfloat16_rn(vv[k]);
        float lo = vv[k] - __bfloat162float(hi);
        g_xhi[o + k] = hi;
        g_xlo[o + k] = __float2bfloat16_rn(lo);
    }
}

__global__ void splitw_kernel(const float* __restrict__ Wc, const float* __restrict__ We)
{
    __shared__ float t[32][33];
    int ez = blockIdx.z;
    const float* src = (ez == 0) ? Wc : (We + (size_t)(ez - 1) * Dd * Uu);
    int u0 = blockIdx.x * 32, d0 = blockIdx.y * 32;
    int tx = threadIdx.x, ty = threadIdx.y;
#pragma unroll
    for (int k = 0; k < 32; k += 8)
        t[ty + k][tx] = src[(size_t)(d0 + ty + k) * Uu + u0 + tx];
    __syncthreads();
#pragma unroll
    for (int k = 0; k < 32; k += 8) {
        int u = u0 + ty + k, d = d0 + tx;
        float v = t[tx][ty + k];
        __nv_bfloat16 hi = __float2bfloat16_rn(v);
        float lo = v - __bfloat162float(hi);
        size_t o = (size_t)ez * Uu * Dd + (size_t)u * Dd + d;
        g_whi[o] = hi;
        g_wlo[o] = __float2bfloat16_rn(lo);
    }
}

// ============================================================
// mma.sync bf16-split GEMM. FIELD=true: loops experts, masked accumulate.
// ============================================================
template<bool FIELD>
__global__ __launch_bounds__(256) void gemm_tc(const float* __restrict__ bias)
{
    extern __shared__ __align__(1024) char dsm[];
    const int tid = threadIdx.x;
    const int w = tid >> 5, lane = tid & 31;
    const int m0 = blockIdx.x * BM;
    const int n0 = blockIdx.y * BN;
    const int f  = FIELD ? blockIdx.z : 0;
    const int wm = (w & 1) * 64;
    const int wn = (w >> 1) * 64;
    uint32_t sb = s2u(dsm);
    float* msk = (float*)(dsm + MSK_OFF);

    if (FIELD) {
        for (int i = tid; i < Ee * BM; i += 256) {
            int e = i >> 7, r = i & 127;
            msk[i] = g_mask[(size_t)(m0 + r) * (Ff * Ee) + f * Ee + e];
        }
    }

    const int lrow = (lane & 7) + ((lane >> 3) & 1) * 8;
    const int kb   = lane >> 4;
    const int E = FIELD ? Ee : 1;

    for (int e = 0; e < E; e++) {
        const int ez = FIELD ? (1 + f * Ee + e) : 0;
        const __nv_bfloat16* wbh = g_whi + (size_t)ez * Uu * Dd;
        const __nv_bfloat16* wbl = g_wlo + (size_t)ez * Uu * Dd;

        float acc[4][8][4];
#pragma unroll
        for (int mi = 0; mi < 4; mi++)
#pragma unroll
            for (int ni = 0; ni < 8; ni++)
#pragma unroll
                for (int j = 0; j < 4; j++) acc[mi][ni][j] = 0.f;

        issue_chunk(sb, 0, 0, wbh, wbl, m0, n0, tid);

        for (int ch = 0; ch < 16; ch++) {
            if (ch + 1 < 16) {
                issue_chunk(sb, (ch + 1) & 1, ch + 1, wbh, wbl, m0, n0, tid);
                CP_WAIT(1);
            } else {
                CP_WAIT(0);
            }
            __syncthreads();

            uint32_t s0 = sb + (uint32_t)(ch & 1) * STAGE;
#pragma unroll
            for (int ks = 0; ks < 4; ks++) {
                uint32_t koff = (uint32_t)(ks * 2 + kb) * 16;
                uint32_t ahi[4][4], alo[4][4], bhi[4][4], blo[4][4];
#pragma unroll
                for (int mi = 0; mi < 4; mi++) {
                    uint32_t ro = (uint32_t)(wm + mi * 16 + lrow) * 128 + koff;
                    ldsm4(ahi[mi], s0 + AHI + SWZ(ro));
                    ldsm4(alo[mi], s0 + ALO + SWZ(ro));
                }
#pragma unroll
                for (int nj = 0; nj < 4; nj++) {
                    uint32_t ro = (uint32_t)(wn + nj * 16 + lrow) * 128 + koff;
                    ldsm4(bhi[nj], s0 + BHI + SWZ(ro));
                    ldsm4(blo[nj], s0 + BLO + SWZ(ro));
                }
#pragma unroll
                for (int mi = 0; mi < 4; mi++)
#pragma unroll
                    for (int nj = 0; nj < 4; nj++) {
                        mma16816(acc[mi][2*nj],   ahi[mi], bhi[nj][0], bhi[nj][2]);
                        mma16816(acc[mi][2*nj+1], ahi[mi], bhi[nj][1], bhi[nj][3]);
                        mma16816(acc[mi][2*nj],   ahi[mi], blo[nj][0], blo[nj][2]);
                        mma16816(acc[mi][2*nj+1], ahi[mi], blo[nj][1], blo[nj][3]);
                        mma16816(acc[mi][2*nj],   alo[mi], bhi[nj][0], bhi[nj][2]);
                        mma16816(acc[mi][2*nj+1], alo[mi], bhi[nj][1], bhi[nj][3]);
                    }
            }
            __syncthreads();
        }

        // epilogue for this expert
        const float* bep = bias + (FIELD ? (size_t)(f * Ee + e) * Uu : 0) + n0;
#pragma unroll
        for (int mi = 0; mi < 4; mi++) {
#pragma unroll
            for (int h = 0; h < 2; h++) {
                int rl = wm + mi * 16 + (lane >> 2) + h * 8;
                int grow = m0 + rl;
                float mk = FIELD ? msk[e * BM + rl] : 1.f;
                float* gp = FIELD
                    ? (g_field + (size_t)grow * (Ff * Uu) + (size_t)f * Uu + n0)
                    : (g_common + (size_t)grow * Uu + n0);
#pragma unroll
                for (int ni = 0; ni < 8; ni++) {
                    int cl = wn + ni * 8 + (lane & 3) * 2;
                    float v0 = acc[mi][ni][h * 2 + 0] + bep[cl];
                    float v1 = acc[mi][ni][h * 2 + 1] + bep[cl + 1];
                    v0 = fmaxf(v0, 0.f) * mk;
                    v1 = fmaxf(v1, 0.f) * mk;
                    float2* p = (float2*)(gp + cl);
                    if (FIELD && e > 0) {
                        float2 old = *p;
                        v0 += old.x; v1 += old.y;
                    }
                    *p = make_float2(v0, v1);
                }
            }
        }
    }
}

// ============================================================
// fused per-row epilogue (unchanged)
// ============================================================
__global__ __launch_bounds__(320) void epilogue_kernel(
    const float* __restrict__ x,
    const float* __restrict__ Wg, const float* __restrict__ bg,
    const float* __restrict__ Wa, const float* __restrict__ ba,
    const float* __restrict__ Wu, const float* __restrict__ bu,
    float* __restrict__ out)
{
    const int b = blockIdx.x;
    __shared__ float xs[Dd];
    __shared__ float cs[Uu];
    __shared__ float fs[Ff][Uu];
    __shared__ float s_att[Ff], s_upd[Ff];
    __shared__ float s_logit[Tt][Gg];
    __shared__ float s_gates[Tt][Gg];

    const int tid = threadIdx.x;
    for (int i = tid; i < Dd; i += 320) xs[i] = x[(size_t)b * Dd + i];
    for (int i = tid; i < Uu; i += 320) cs[i] = g_common[(size_t)b * Uu + i];
    for (int i = tid; i < Ff * Uu; i += 320) fs[0][i] = g_field[(size_t)b * Ff * Uu + i];
    __syncthreads();

    const int w = tid >> 5, lane = tid & 31;

    if (w < 8) {
        int f = w >> 1;
        const float* Wv = (w & 1) ? (Wu + (size_t)f * 2 * Uu) : (Wa + (size_t)f * 2 * Uu);
        float s = 0.f;
        for (int k = lane; k < Uu; k += 32) s = fmaf(cs[k],    Wv[k],      s);
        for (int k = lane; k < Uu; k += 32) s = fmaf(fs[f][k], Wv[Uu + k], s);
#pragma unroll
        for (int o = 16; o; o >>= 1) s += __shfl_xor_sync(0xffffffffu, s, o);
        if (lane == 0) {
            float bv = (w & 1) ? bu[f] : ba[f];
            float v = 1.f / (1.f + expf(-(s + bv)));
            if (w & 1) s_upd[f] = v; else s_att[f] = v;
        }
    }
    {
        int t = w / Gg, g = w - t * Gg;
        float s = 0.f;
        for (int d = lane; d < Dd; d += 32)
            s = fmaf(xs[d], Wg[((size_t)t * Dd + d) * Gg + g], s);
#pragma unroll
        for (int o = 16; o; o >>= 1) s += __shfl_xor_sync(0xffffffffu, s, o);
        if (lane == 0) s_logit[t][g] = s + bg[t * Gg + g];
    }
    __syncthreads();

    if (tid < Tt) {
        float mx = s_logit[tid][0];
#pragma unroll
        for (int g = 1; g < Gg; g++) mx = fmaxf(mx, s_logit[tid][g]);
        float ex[Gg], sum = 0.f;
#pragma unroll
        for (int g = 0; g < Gg; g++) { ex[g] = expf(s_logit[tid][g] - mx); sum += ex[g]; }
        float inv = 1.f / sum;
#pragma unroll
        for (int g = 0; g < Gg; g++) s_gates[tid][g] = ex[g] * inv;
    }
    __syncthreads();

    for (int u = tid; u < Uu; u += 320) {
        float c = cs[u];
        float ffv[Ff];
#pragma unroll
        for (int f = 0; f < Ff; f++) {
            float fo = fs[f][u];
            float fa = s_att[f] * fo;
            ffv[f] = s_upd[f] * fa + (1.f - s_upd[f]) * c;
        }
#pragma unroll
        for (int t = 0; t < Tt; t++) {
            float o = s_gates[t][0] * c;
#pragma unroll
            for (int fq = 0; fq < Ff; fq++) o = fmaf(s_gates[t][1 + fq], ffv[fq], o);
            out[((size_t)b * Tt + t) * Uu + u] = o;
        }
    }
}

// ============================================================
// launch
// ============================================================
extern "C" void kernel_launch(void* const* d_in, const int* in_sizes, int n_in,
                              void* d_out, int out_size)
{
    const float* x  = (const float*)d_in[0];
    const float* Wc = (const float*)d_in[1];
    const float* bc = (const float*)d_in[2];
    const float* We = (const float*)d_in[3];
    const float* be = (const float*)d_in[4];
    const float* Wg = (const float*)d_in[5];
    const float* bg = (const float*)d_in[6];
    const float* Wa = (const float*)d_in[7];
    const float* ba = (const float*)d_in[8];
    const float* Wu = (const float*)d_in[9];
    const float* bu = (const float*)d_in[10];
    float* out = (float*)d_out;

    cudaFuncSetAttribute(gemm_tc<false>, cudaFuncAttributeMaxDynamicSharedMemorySize, DSM_TOTAL);
    cudaFuncSetAttribute(gemm_tc<true>,  cudaFuncAttributeMaxDynamicSharedMemorySize, DSM_TOTAL);

    mask_kernel<<<Bsz / 256, 256>>>(x);
    splitx_kernel<<<(Bsz * Dd / 4) / 256, 256>>>(x);
    splitw_kernel<<<dim3(Uu / 32, Dd / 32, NEXP), dim3(32, 8)>>>(Wc, We);
    gemm_tc<false><<<dim3(Bsz / BM, Uu / BN), 256, DSM_TOTAL>>>(bc);
    gemm_tc<true> <<<dim3(Bsz / BM, Uu / BN, Ff), 256, DSM_TOTAL>>>(be);
    epilogue_kernel<<<Bsz, 320>>>(x, Wg, bg, Wa, ba, Wu, bu, out);
}

// round 6
// speedup vs baseline: 4.9308x; 1.9608x over previous
#include <cuda_runtime.h>
#include <cuda_bf16.h>
#include <math.h>
#include <stdint.h>

// ---------------- problem constants ----------------
#define Bsz 8192
#define Dd  1024
#define Uu  512
#define Ff  4
#define Ee  4
#define Tt  2
#define Gg  5
#define NEXP 17

// ---------------- scratch ----------------
__device__ float g_common[Bsz * Uu];
__device__ float g_field [Bsz * Ff * Uu];
__device__ int   g_idx[Ff * Ee][Bsz];      // compacted active-row lists
__device__ int   g_cnt[Ff * Ee];
__device__ __nv_bfloat16 g_xhi[Bsz * Dd];
__device__ __nv_bfloat16 g_xlo[Bsz * Dd];
__device__ __nv_bfloat16 g_whi[(size_t)NEXP * Uu * Dd];   // [ez][u][d]
__device__ __nv_bfloat16 g_wlo[(size_t)NEXP * Uu * Dd];

// ---------------- GEMM config ----------------
#define BM 128
#define BN 256
#define BK 64
#define AHI 0
#define ALO 16384
#define BHI 32768
#define BLO 65536
#define STAGE 98304
#define IDX_OFF (2 * STAGE)
#define DSM_TOTAL (2 * STAGE + 1024)

#define SWZ(o) ((o) ^ (((o) >> 3) & 0x70))

__device__ __forceinline__ uint32_t s2u(const void* p) {
    return (uint32_t)__cvta_generic_to_shared(p);
}

__device__ __forceinline__ void cpa16(uint32_t dst, const void* src) {
    asm volatile("cp.async.cg.shared.global [%0], [%1], 16;"
                 :: "r"(dst), "l"(__cvta_generic_to_global(src)));
}
#define CP_COMMIT() asm volatile("cp.async.commit_group;" ::: "memory")
#define CP_WAIT(n)  asm volatile("cp.async.wait_group %0;" :: "n"(n) : "memory")

__device__ __forceinline__ void ldsm4(uint32_t* r, uint32_t addr) {
    asm volatile("ldmatrix.sync.aligned.m8n8.x4.shared.b16 {%0,%1,%2,%3}, [%4];"
                 : "=r"(r[0]), "=r"(r[1]), "=r"(r[2]), "=r"(r[3]) : "r"(addr));
}

__device__ __forceinline__ void mma16816(float* c, const uint32_t* a, uint32_t b0, uint32_t b1) {
    asm volatile(
        "mma.sync.aligned.m16n8k16.row.col.f32.bf16.bf16.f32 "
        "{%0,%1,%2,%3}, {%4,%5,%6,%7}, {%8,%9}, {%0,%1,%2,%3};"
        : "+f"(c[0]), "+f"(c[1]), "+f"(c[2]), "+f"(c[3])
        : "r"(a[0]), "r"(a[1]), "r"(a[2]), "r"(a[3]), "r"(b0), "r"(b1));
}

// issue one k-chunk's cp.async loads. sidx==nullptr -> identity rows m0+r.
__device__ __forceinline__ void issue_chunk(uint32_t sb, int buf, int ch,
                                            const __nv_bfloat16* __restrict__ wbh,
                                            const __nv_bfloat16* __restrict__ wbl,
                                            const int* __restrict__ sidx,
                                            int m0, int n0, int tid)
{
    uint32_t st = sb + (uint32_t)buf * STAGE;
#pragma unroll
    for (int i = 0; i < 4; i++) {
        int u = tid + i * 256, r = u >> 3, cc = u & 7;
        int grow = sidx ? sidx[r] : (m0 + r);
        size_t go = (size_t)grow * Dd + ch * 64 + cc * 8;
        uint32_t so = SWZ(r * 128 + cc * 16);
        cpa16(st + AHI + so, g_xhi + go);
        cpa16(st + ALO + so, g_xlo + go);
    }
#pragma unroll
    for (int i = 0; i < 8; i++) {
        int u = tid + i * 256, r = u >> 3, cc = u & 7;
        size_t go = (size_t)(n0 + r) * Dd + ch * 64 + cc * 8;
        uint32_t so = SWZ(r * 128 + cc * 16);
        cpa16(st + BHI + so, wbh + go);
        cpa16(st + BLO + so, wbl + go);
    }
    CP_COMMIT();
}

// ============================================================
// prep kernels
// ============================================================
__global__ void zero_kernel()
{
    size_t i = (size_t)blockIdx.x * blockDim.x + threadIdx.x;
    ((float4*)g_field)[i] = make_float4(0.f, 0.f, 0.f, 0.f);
    if (i < Ff * Ee) g_cnt[i] = 0;
}

__global__ void build_idx(const float* __restrict__ x)
{
    int b = blockIdx.x * blockDim.x + threadIdx.x;
    if (b >= Bsz) return;
    const float* xr = x + (size_t)b * Dd;
#pragma unroll
    for (int f = 0; f < 2; f++)
#pragma unroll
        for (int e = 0; e < 4; e++)
            if (xr[f * 4 + e] > 0.f) {
                int p = atomicAdd(&g_cnt[f * 4 + e], 1);
                g_idx[f * 4 + e][p] = b;
            }
#pragma unroll
    for (int f = 2; f < 4; f++) {
        float v = xr[8 + (f - 2)];
        int e = (v <= -0.5f) ? 0 : (v <= 0.f) ? 1 : (v <= 0.5f) ? 2 : 3;
        int p = atomicAdd(&g_cnt[f * 4 + e], 1);
        g_idx[f * 4 + e][p] = b;
    }
}

__global__ void splitx_kernel(const float* __restrict__ x)
{
    int i = blockIdx.x * blockDim.x + threadIdx.x;
    float4 v = ((const float4*)x)[i];
    int o = i * 4;
    float vv[4] = {v.x, v.y, v.z, v.w};
#pragma unroll
    for (int k = 0; k < 4; k++) {
        __nv_bfloat16 hi = __float2bfloat16_rn(vv[k]);
        float lo = vv[k] - __bfloat162float(hi);
        g_xhi[o + k] = hi;
        g_xlo[o + k] = __float2bfloat16_rn(lo);
    }
}

__global__ void splitw_kernel(const float* __restrict__ Wc, const float* __restrict__ We)
{
    __shared__ float t[32][33];
    int ez = blockIdx.z;
    const float* src = (ez == 0) ? Wc : (We + (size_t)(ez - 1) * Dd * Uu);
    int u0 = blockIdx.x * 32, d0 = blockIdx.y * 32;
    int tx = threadIdx.x, ty = threadIdx.y;
#pragma unroll
    for (int k = 0; k < 32; k += 8)
        t[ty + k][tx] = src[(size_t)(d0 + ty + k) * Uu + u0 + tx];
    __syncthreads();
#pragma unroll
    for (int k = 0; k < 32; k += 8) {
        int u = u0 + ty + k, d = d0 + tx;
        float v = t[tx][ty + k];
        __nv_bfloat16 hi = __float2bfloat16_rn(v);
        float lo = v - __bfloat162float(hi);
        size_t o = (size_t)ez * Uu * Dd + (size_t)u * Dd + d;
        g_whi[o] = hi;
        g_wlo[o] = __float2bfloat16_rn(lo);
    }
}

// ============================================================
// shared GEMM mainloop (bf16 3-term split), then per-variant epilogue
// ============================================================
__device__ __forceinline__ void gemm_mainloop(
    uint32_t sb, const __nv_bfloat16* wbh, const __nv_bfloat16* wbl,
    const int* sidx, int m0, int n0, int tid, int lane, int wm, int wn,
    float acc[4][8][4])
{
    const int lrow = (lane & 7) + ((lane >> 3) & 1) * 8;
    const int kb   = lane >> 4;

    issue_chunk(sb, 0, 0, wbh, wbl, sidx, m0, n0, tid);

    for (int ch = 0; ch < 16; ch++) {
        if (ch + 1 < 16) {
            issue_chunk(sb, (ch + 1) & 1, ch + 1, wbh, wbl, sidx, m0, n0, tid);
            CP_WAIT(1);
        } else {
            CP_WAIT(0);
        }
        __syncthreads();

        uint32_t s0 = sb + (uint32_t)(ch & 1) * STAGE;
#pragma unroll
        for (int ks = 0; ks < 4; ks++) {
            uint32_t koff = (uint32_t)(ks * 2 + kb) * 16;
            uint32_t ahi[4][4], alo[4][4], bhi[4][4], blo[4][4];
#pragma unroll
            for (int mi = 0; mi < 4; mi++) {
                uint32_t ro = (uint32_t)(wm + mi * 16 + lrow) * 128 + koff;
                ldsm4(ahi[mi], s0 + AHI + SWZ(ro));
                ldsm4(alo[mi], s0 + ALO + SWZ(ro));
            }
#pragma unroll
            for (int nj = 0; nj < 4; nj++) {
                uint32_t ro = (uint32_t)(wn + nj * 16 + lrow) * 128 + koff;
                ldsm4(bhi[nj], s0 + BHI + SWZ(ro));
                ldsm4(blo[nj], s0 + BLO + SWZ(ro));
            }
#pragma unroll
            for (int mi = 0; mi < 4; mi++)
#pragma unroll
                for (int nj = 0; nj < 4; nj++) {
                    mma16816(acc[mi][2*nj],   ahi[mi], bhi[nj][0], bhi[nj][2]);
                    mma16816(acc[mi][2*nj+1], ahi[mi], bhi[nj][1], bhi[nj][3]);
                    mma16816(acc[mi][2*nj],   ahi[mi], blo[nj][0], blo[nj][2]);
                    mma16816(acc[mi][2*nj+1], ahi[mi], blo[nj][1], blo[nj][3]);
                    mma16816(acc[mi][2*nj],   alo[mi], bhi[nj][0], bhi[nj][2]);
                    mma16816(acc[mi][2*nj+1], alo[mi], bhi[nj][1], bhi[nj][3]);
                }
        }
        __syncthreads();
    }
}

// ---------------- dense GEMM: common expert ----------------
__global__ __launch_bounds__(256) void gemm_common(const float* __restrict__ bc)
{
    extern __shared__ __align__(1024) char dsm[];
    const int tid = threadIdx.x;
    const int w = tid >> 5, lane = tid & 31;
    const int m0 = blockIdx.x * BM;
    const int n0 = blockIdx.y * BN;
    const int wm = (w & 1) * 64;
    const int wn = (w >> 1) * 64;
    uint32_t sb = s2u(dsm);

    float acc[4][8][4];
#pragma unroll
    for (int mi = 0; mi < 4; mi++)
#pragma unroll
        for (int ni = 0; ni < 8; ni++)
#pragma unroll
            for (int j = 0; j < 4; j++) acc[mi][ni][j] = 0.f;

    gemm_mainloop(sb, g_whi, g_wlo, nullptr, m0, n0, tid, lane, wm, wn, acc);

    const float* bep = bc + n0;
#pragma unroll
    for (int mi = 0; mi < 4; mi++) {
#pragma unroll
        for (int h = 0; h < 2; h++) {
            int rl = wm + mi * 16 + (lane >> 2) + h * 8;
            float* gp = g_common + (size_t)(m0 + rl) * Uu + n0;
#pragma unroll
            for (int ni = 0; ni < 8; ni++) {
                int cl = wn + ni * 8 + (lane & 3) * 2;
                float v0 = fmaxf(acc[mi][ni][h * 2 + 0] + bep[cl],     0.f);
                float v1 = fmaxf(acc[mi][ni][h * 2 + 1] + bep[cl + 1], 0.f);
                *(float2*)(gp + cl) = make_float2(v0, v1);
            }
        }
    }
}

// ---------------- sparse GEMM: field experts, gathered rows ----------------
__global__ __launch_bounds__(256) void gemm_sparse(const float* __restrict__ be)
{
    extern __shared__ __align__(1024) char dsm[];
    const int fe = blockIdx.z;
    const int f = fe >> 2;
    const int cnt = g_cnt[fe];
    const int t0 = blockIdx.x * BM;
    if (t0 >= cnt) return;

    const int tid = threadIdx.x;
    const int w = tid >> 5, lane = tid & 31;
    const int n0 = blockIdx.y * BN;
    const int wm = (w & 1) * 64;
    const int wn = (w >> 1) * 64;
    uint32_t sb = s2u(dsm);
    int* sidx = (int*)(dsm + IDX_OFF);

    // load compacted row indices (pad with last valid row; padded slots don't write)
    if (tid < BM) {
        int s = t0 + tid;
        sidx[tid] = g_idx[fe][(s < cnt) ? s : (cnt - 1)];
    }
    __syncthreads();

    const __nv_bfloat16* wbh = g_whi + (size_t)(1 + fe) * Uu * Dd;
    const __nv_bfloat16* wbl = g_wlo + (size_t)(1 + fe) * Uu * Dd;

    float acc[4][8][4];
#pragma unroll
    for (int mi = 0; mi < 4; mi++)
#pragma unroll
        for (int ni = 0; ni < 8; ni++)
#pragma unroll
            for (int j = 0; j < 4; j++) acc[mi][ni][j] = 0.f;

    gemm_mainloop(sb, wbh, wbl, sidx, 0, n0, tid, lane, wm, wn, acc);

    // epilogue: bias + relu; continuous fields (f>=2) partition rows -> store;
    // discrete fields (f<2) may overlap across experts -> atomic add
    const float* bep = be + (size_t)fe * Uu + n0;
    const bool atom = (f < 2);
#pragma unroll
    for (int mi = 0; mi < 4; mi++) {
#pragma unroll
        for (int h = 0; h < 2; h++) {
            int rl = wm + mi * 16 + (lane >> 2) + h * 8;
            if (t0 + rl >= cnt) continue;
            int grow = sidx[rl];
            float* gp = g_field + (size_t)grow * (Ff * Uu) + (size_t)f * Uu + n0;
#pragma unroll
            for (int ni = 0; ni < 8; ni++) {
                int cl = wn + ni * 8 + (lane & 3) * 2;
                float v0 = fmaxf(acc[mi][ni][h * 2 + 0] + bep[cl],     0.f);
                float v1 = fmaxf(acc[mi][ni][h * 2 + 1] + bep[cl + 1], 0.f);
                if (atom) {
                    atomicAdd(gp + cl,     v0);
                    atomicAdd(gp + cl + 1, v1);
                } else {
                    *(float2*)(gp + cl) = make_float2(v0, v1);
                }
            }
        }
    }
}

// ============================================================
// fused per-row epilogue (unchanged)
// ============================================================
__global__ __launch_bounds__(320) void epilogue_kernel(
    const float* __restrict__ x,
    const float* __restrict__ Wg, const float* __restrict__ bg,
    const float* __restrict__ Wa, const float* __restrict__ ba,
    const float* __restrict__ Wu, const float* __restrict__ bu,
    float* __restrict__ out)
{
    const int b = blockIdx.x;
    __shared__ float xs[Dd];
    __shared__ float cs[Uu];
    __shared__ float fs[Ff][Uu];
    __shared__ float s_att[Ff], s_upd[Ff];
    __shared__ float s_logit[Tt][Gg];
    __shared__ float s_gates[Tt][Gg];

    const int tid = threadIdx.x;
    for (int i = tid; i < Dd; i += 320) xs[i] = x[(size_t)b * Dd + i];
    for (int i = tid; i < Uu; i += 320) cs[i] = g_common[(size_t)b * Uu + i];
    for (int i = tid; i < Ff * Uu; i += 320) fs[0][i] = g_field[(size_t)b * Ff * Uu + i];
    __syncthreads();

    const int w = tid >> 5, lane = tid & 31;

    if (w < 8) {
        int f = w >> 1;
        const float* Wv = (w & 1) ? (Wu + (size_t)f * 2 * Uu) : (Wa + (size_t)f * 2 * Uu);
        float s = 0.f;
        for (int k = lane; k < Uu; k += 32) s = fmaf(cs[k],    Wv[k],      s);
        for (int k = lane; k < Uu; k += 32) s = fmaf(fs[f][k], Wv[Uu + k], s);
#pragma unroll
        for (int o = 16; o; o >>= 1) s += __shfl_xor_sync(0xffffffffu, s, o);
        if (lane == 0) {
            float bv = (w & 1) ? bu[f] : ba[f];
            float v = 1.f / (1.f + expf(-(s + bv)));
            if (w & 1) s_upd[f] = v; else s_att[f] = v;
        }
    }
    {
        int t = w / Gg, g = w - t * Gg;
        float s = 0.f;
        for (int d = lane; d < Dd; d += 32)
            s = fmaf(xs[d], Wg[((size_t)t * Dd + d) * Gg + g], s);
#pragma unroll
        for (int o = 16; o; o >>= 1) s += __shfl_xor_sync(0xffffffffu, s, o);
        if (lane == 0) s_logit[t][g] = s + bg[t * Gg + g];
    }
    __syncthreads();

    if (tid < Tt) {
        float mx = s_logit[tid][0];
#pragma unroll
        for (int g = 1; g < Gg; g++) mx = fmaxf(mx, s_logit[tid][g]);
        float ex[Gg], sum = 0.f;
#pragma unroll
        for (int g = 0; g < Gg; g++) { ex[g] = expf(s_logit[tid][g] - mx); sum += ex[g]; }
        float inv = 1.f / sum;
#pragma unroll
        for (int g = 0; g < Gg; g++) s_gates[tid][g] = ex[g] * inv;
    }
    __syncthreads();

    for (int u = tid; u < Uu; u += 320) {
        float c = cs[u];
        float ffv[Ff];
#pragma unroll
        for (int f = 0; f < Ff; f++) {
            float fo = fs[f][u];
            float fa = s_att[f] * fo;
            ffv[f] = s_upd[f] * fa + (1.f - s_upd[f]) * c;
        }
#pragma unroll
        for (int t = 0; t < Tt; t++) {
            float o = s_gates[t][0] * c;
#pragma unroll
            for (int fq = 0; fq < Ff; fq++) o = fmaf(s_gates[t][1 + fq], ffv[fq], o);
            out[((size_t)b * Tt + t) * Uu + u] = o;
        }
    }
}

// ============================================================
// launch
// ============================================================
extern "C" void kernel_launch(void* const* d_in, const int* in_sizes, int n_in,
                              void* d_out, int out_size)
{
    const float* x  = (const float*)d_in[0];
    const float* Wc = (const float*)d_in[1];
    const float* bc = (const float*)d_in[2];
    const float* We = (const float*)d_in[3];
    const float* be = (const float*)d_in[4];
    const float* Wg = (const float*)d_in[5];
    const float* bg = (const float*)d_in[6];
    const float* Wa = (const float*)d_in[7];
    const float* ba = (const float*)d_in[8];
    const float* Wu = (const float*)d_in[9];
    const float* bu = (const float*)d_in[10];
    float* out = (float*)d_out;

    cudaFuncSetAttribute(gemm_common, cudaFuncAttributeMaxDynamicSharedMemorySize, DSM_TOTAL);
    cudaFuncSetAttribute(gemm_sparse, cudaFuncAttributeMaxDynamicSharedMemorySize, DSM_TOTAL);

    zero_kernel<<<(Bsz * Ff * Uu / 4) / 256, 256>>>();
    build_idx<<<Bsz / 256, 256>>>(x);
    splitx_kernel<<<(Bsz * Dd / 4) / 256, 256>>>(x);
    splitw_kernel<<<dim3(Uu / 32, Dd / 32, NEXP), dim3(32, 8)>>>(Wc, We);
    gemm_common<<<dim3(Bsz / BM, Uu / BN), 256, DSM_TOTAL>>>(bc);
    gemm_sparse<<<dim3(Bsz / BM, Uu / BN, Ff * Ee), 256, DSM_TOTAL>>>(be);
    epilogue_kernel<<<Bsz, 320>>>(x, Wg, bg, Wa, ba, Wu, bu, out);
}

// round 7
// speedup vs baseline: 5.4441x; 1.1041x over previous
#include <cuda_runtime.h>
#include <cuda_bf16.h>
#include <math.h>
#include <stdint.h>

// ---------------- problem constants ----------------
#define Bsz 8192
#define Dd  1024
#define Uu  512
#define Ff  4
#define Ee  4
#define Tt  2
#define Gg  5
#define NEXP 17

// ---------------- scratch ----------------
__device__ float g_common[Bsz * Uu];
__device__ float g_field [Bsz * Ff * Uu];
__device__ float g_logits[Bsz * Tt * Gg];
__device__ int   g_idx[Ff * Ee][Bsz];      // compacted active-row lists
__device__ int   g_cnt[Ff * Ee];
__device__ __nv_bfloat16 g_xhi[Bsz * Dd];
__device__ __nv_bfloat16 g_xlo[Bsz * Dd];
__device__ __nv_bfloat16 g_whi[(size_t)NEXP * Uu * Dd];   // [ez][u][d]
__device__ __nv_bfloat16 g_wlo[(size_t)NEXP * Uu * Dd];

// ---------------- GEMM config ----------------
#define BM 128
#define BN 256
#define BK 64
#define AHI 0
#define ALO 16384
#define BHI 32768
#define BLO 65536
#define STAGE 98304
#define IDX_OFF (2 * STAGE)
#define DSM_TOTAL (2 * STAGE + 1024)

#define SWZ(o) ((o) ^ (((o) >> 3) & 0x70))

__device__ __forceinline__ uint32_t s2u(const void* p) {
    return (uint32_t)__cvta_generic_to_shared(p);
}

__device__ __forceinline__ void cpa16(uint32_t dst, const void* src) {
    asm volatile("cp.async.cg.shared.global [%0], [%1], 16;"
                 :: "r"(dst), "l"(__cvta_generic_to_global(src)));
}
#define CP_COMMIT() asm volatile("cp.async.commit_group;" ::: "memory")
#define CP_WAIT(n)  asm volatile("cp.async.wait_group %0;" :: "n"(n) : "memory")

__device__ __forceinline__ void ldsm4(uint32_t* r, uint32_t addr) {
    asm volatile("ldmatrix.sync.aligned.m8n8.x4.shared.b16 {%0,%1,%2,%3}, [%4];"
                 : "=r"(r[0]), "=r"(r[1]), "=r"(r[2]), "=r"(r[3]) : "r"(addr));
}

__device__ __forceinline__ void mma16816(float* c, const uint32_t* a, uint32_t b0, uint32_t b1) {
    asm volatile(
        "mma.sync.aligned.m16n8k16.row.col.f32.bf16.bf16.f32 "
        "{%0,%1,%2,%3}, {%4,%5,%6,%7}, {%8,%9}, {%0,%1,%2,%3};"
        : "+f"(c[0]), "+f"(c[1]), "+f"(c[2]), "+f"(c[3])
        : "r"(a[0]), "r"(a[1]), "r"(a[2]), "r"(a[3]), "r"(b0), "r"(b1));
}

// issue one k-chunk's cp.async loads. sidx==nullptr -> identity rows m0+r.
__device__ __forceinline__ void issue_chunk(uint32_t sb, int buf, int ch,
                                            const __nv_bfloat16* __restrict__ wbh,
                                            const __nv_bfloat16* __restrict__ wbl,
                                            const int* __restrict__ sidx,
                                            int m0, int n0, int tid)
{
    uint32_t st = sb + (uint32_t)buf * STAGE;
#pragma unroll
    for (int i = 0; i < 4; i++) {
        int u = tid + i * 256, r = u >> 3, cc = u & 7;
        int grow = sidx ? sidx[r] : (m0 + r);
        size_t go = (size_t)grow * Dd + ch * 64 + cc * 8;
        uint32_t so = SWZ(r * 128 + cc * 16);
        cpa16(st + AHI + so, g_xhi + go);
        cpa16(st + ALO + so, g_xlo + go);
    }
#pragma unroll
    for (int i = 0; i < 8; i++) {
        int u = tid + i * 256, r = u >> 3, cc = u & 7;
        size_t go = (size_t)(n0 + r) * Dd + ch * 64 + cc * 8;
        uint32_t so = SWZ(r * 128 + cc * 16);
        cpa16(st + BHI + so, wbh + go);
        cpa16(st + BLO + so, wbl + go);
    }
    CP_COMMIT();
}

// ============================================================
// prep kernels
// ============================================================
// zero only discrete-field (f=0,1) half of g_field + counters
__global__ void zero_kernel()
{
    int i = blockIdx.x * blockDim.x + threadIdx.x;     // float4 index, Bsz*2*Uu/4 total
    int b = i >> 8, r = i & 255;                       // 256 float4 per row-half
    ((float4*)g_field)[(size_t)b * (Ff * Uu / 4) + r] = make_float4(0.f, 0.f, 0.f, 0.f);
    if (i < Ff * Ee) g_cnt[i] = 0;
}

__global__ void build_idx(const float* __restrict__ x)
{
    int b = blockIdx.x * blockDim.x + threadIdx.x;
    if (b >= Bsz) return;
    const float* xr = x + (size_t)b * Dd;
#pragma unroll
    for (int f = 0; f < 2; f++)
#pragma unroll
        for (int e = 0; e < 4; e++)
            if (xr[f * 4 + e] > 0.f) {
                int p = atomicAdd(&g_cnt[f * 4 + e], 1);
                g_idx[f * 4 + e][p] = b;
            }
#pragma unroll
    for (int f = 2; f < 4; f++) {
        float v = xr[8 + (f - 2)];
        int e = (v <= -0.5f) ? 0 : (v <= 0.f) ? 1 : (v <= 0.5f) ? 2 : 3;
        int p = atomicAdd(&g_cnt[f * 4 + e], 1);
        g_idx[f * 4 + e][p] = b;
    }
}

__global__ void splitx_kernel(const float* __restrict__ x)
{
    int i = blockIdx.x * blockDim.x + threadIdx.x;
    float4 v = ((const float4*)x)[i];
    int o = i * 4;
    float vv[4] = {v.x, v.y, v.z, v.w};
#pragma unroll
    for (int k = 0; k < 4; k++) {
        __nv_bfloat16 hi = __float2bfloat16_rn(vv[k]);
        float lo = vv[k] - __bfloat162float(hi);
        g_xhi[o + k] = hi;
        g_xlo[o + k] = __float2bfloat16_rn(lo);
    }
}

__global__ void splitw_kernel(const float* __restrict__ Wc, const float* __restrict__ We)
{
    __shared__ float t[32][33];
    int ez = blockIdx.z;
    const float* src = (ez == 0) ? Wc : (We + (size_t)(ez - 1) * Dd * Uu);
    int u0 = blockIdx.x * 32, d0 = blockIdx.y * 32;
    int tx = threadIdx.x, ty = threadIdx.y;
#pragma unroll
    for (int k = 0; k < 32; k += 8)
        t[ty + k][tx] = src[(size_t)(d0 + ty + k) * Uu + u0 + tx];
    __syncthreads();
#pragma unroll
    for (int k = 0; k < 32; k += 8) {
        int u = u0 + ty + k, d = d0 + tx;
        float v = t[tx][ty + k];
        __nv_bfloat16 hi = __float2bfloat16_rn(v);
        float lo = v - __bfloat162float(hi);
        size_t o = (size_t)ez * Uu * Dd + (size_t)u * Dd + d;
        g_whi[o] = hi;
        g_wlo[o] = __float2bfloat16_rn(lo);
    }
}

// gate logits: g_logits[b][t][g] = x[b,:] . Wg[t,:,g] + bg[t,g]
// 8 warps/block, one row per warp, Wg staged in smem as [d][t*5+g]
__global__ __launch_bounds__(256) void glogits_kernel(
    const float* __restrict__ x, const float* __restrict__ Wg,
    const float* __restrict__ bg)
{
    __shared__ float wgs[Dd * Tt * Gg / 1];   // 1024*10 floats = 40KB
    const int tid = threadIdx.x;
    for (int i = tid; i < Dd * Tt * Gg; i += 256) {
        int d = i / (Tt * Gg), tg = i - d * (Tt * Gg);
        int t = tg / Gg, g = tg - t * Gg;
        wgs[d * (Tt * Gg) + tg] = Wg[((size_t)t * Dd + d) * Gg + g];
    }
    __syncthreads();

    const int w = tid >> 5, lane = tid & 31;
    int b = blockIdx.x * 8 + w;
    const float* xr = x + (size_t)b * Dd;
    float acc[Tt * Gg];
#pragma unroll
    for (int j = 0; j < Tt * Gg; j++) acc[j] = 0.f;
    for (int k = lane; k < Dd; k += 32) {
        float xv = xr[k];
        const float* wr = wgs + k * (Tt * Gg);
#pragma unroll
        for (int j = 0; j < Tt * Gg; j++) acc[j] = fmaf(xv, wr[j], acc[j]);
    }
#pragma unroll
    for (int j = 0; j < Tt * Gg; j++) {
#pragma unroll
        for (int o = 16; o; o >>= 1) acc[j] += __shfl_xor_sync(0xffffffffu, acc[j], o);
    }
    if (lane < Tt * Gg) {
        int t = lane / Gg, g = lane - t * Gg;
        g_logits[(size_t)b * (Tt * Gg) + lane] = acc[lane] + bg[t * Gg + g];
    }
}

// ============================================================
// shared GEMM mainloop (bf16 3-term split)
// ============================================================
__device__ __forceinline__ void gemm_mainloop(
    uint32_t sb, const __nv_bfloat16* wbh, const __nv_bfloat16* wbl,
    const int* sidx, int m0, int n0, int tid, int lane, int wm, int wn,
    float acc[4][8][4])
{
    const int lrow = (lane & 7) + ((lane >> 3) & 1) * 8;
    const int kb   = lane >> 4;

    issue_chunk(sb, 0, 0, wbh, wbl, sidx, m0, n0, tid);

    for (int ch = 0; ch < 16; ch++) {
        if (ch + 1 < 16) {
            issue_chunk(sb, (ch + 1) & 1, ch + 1, wbh, wbl, sidx, m0, n0, tid);
            CP_WAIT(1);
        } else {
            CP_WAIT(0);
        }
        __syncthreads();

        uint32_t s0 = sb + (uint32_t)(ch & 1) * STAGE;
#pragma unroll
        for (int ks = 0; ks < 4; ks++) {
            uint32_t koff = (uint32_t)(ks * 2 + kb) * 16;
            uint32_t ahi[4][4], alo[4][4], bhi[4][4], blo[4][4];
#pragma unroll
            for (int mi = 0; mi < 4; mi++) {
                uint32_t ro = (uint32_t)(wm + mi * 16 + lrow) * 128 + koff;
                ldsm4(ahi[mi], s0 + AHI + SWZ(ro));
                ldsm4(alo[mi], s0 + ALO + SWZ(ro));
            }
#pragma unroll
            for (int nj = 0; nj < 4; nj++) {
                uint32_t ro = (uint32_t)(wn + nj * 16 + lrow) * 128 + koff;
                ldsm4(bhi[nj], s0 + BHI + SWZ(ro));
                ldsm4(blo[nj], s0 + BLO + SWZ(ro));
            }
#pragma unroll
            for (int mi = 0; mi < 4; mi++)
#pragma unroll
                for (int nj = 0; nj < 4; nj++) {
                    mma16816(acc[mi][2*nj],   ahi[mi], bhi[nj][0], bhi[nj][2]);
                    mma16816(acc[mi][2*nj+1], ahi[mi], bhi[nj][1], bhi[nj][3]);
                    mma16816(acc[mi][2*nj],   ahi[mi], blo[nj][0], blo[nj][2]);
                    mma16816(acc[mi][2*nj+1], ahi[mi], blo[nj][1], blo[nj][3]);
                    mma16816(acc[mi][2*nj],   alo[mi], bhi[nj][0], bhi[nj][2]);
                    mma16816(acc[mi][2*nj+1], alo[mi], bhi[nj][1], bhi[nj][3]);
                }
        }
        __syncthreads();
    }
}

// ---------------- merged GEMM: z=0 common (dense), z>=1 expert (gathered) ----
__global__ __launch_bounds__(256) void gemm_all(
    const float* __restrict__ bc, const float* __restrict__ be)
{
    extern __shared__ __align__(1024) char dsm[];
    const int z = blockIdx.z;
    const bool dense = (z == 0);
    const int fe = z - 1;
    const int t0 = blockIdx.x * BM;
    int cnt = 0;
    if (!dense) {
        cnt = g_cnt[fe];
        if (t0 >= cnt) return;
    }

    const int tid = threadIdx.x;
    const int w = tid >> 5, lane = tid & 31;
    const int n0 = blockIdx.y * BN;
    const int wm = (w & 1) * 64;
    const int wn = (w >> 1) * 64;
    uint32_t sb = s2u(dsm);
    int* sidx = (int*)(dsm + IDX_OFF);

    if (!dense) {
        if (tid < BM) {
            int s = t0 + tid;
            sidx[tid] = g_idx[fe][(s < cnt) ? s : (cnt - 1)];
        }
        __syncthreads();
    }

    const int ez = dense ? 0 : (1 + fe);
    const __nv_bfloat16* wbh = g_whi + (size_t)ez * Uu * Dd;
    const __nv_bfloat16* wbl = g_wlo + (size_t)ez * Uu * Dd;

    float acc[4][8][4];
#pragma unroll
    for (int mi = 0; mi < 4; mi++)
#pragma unroll
        for (int ni = 0; ni < 8; ni++)
#pragma unroll
            for (int j = 0; j < 4; j++) acc[mi][ni][j] = 0.f;

    gemm_mainloop(sb, wbh, wbl, dense ? nullptr : sidx, t0, n0, tid, lane, wm, wn, acc);

    if (dense) {
        const float* bep = bc + n0;
#pragma unroll
        for (int mi = 0; mi < 4; mi++) {
#pragma unroll
            for (int h = 0; h < 2; h++) {
                int rl = wm + mi * 16 + (lane >> 2) + h * 8;
                float* gp = g_common + (size_t)(t0 + rl) * Uu + n0;
#pragma unroll
                for (int ni = 0; ni < 8; ni++) {
                    int cl = wn + ni * 8 + (lane & 3) * 2;
                    float v0 = fmaxf(acc[mi][ni][h * 2 + 0] + bep[cl],     0.f);
                    float v1 = fmaxf(acc[mi][ni][h * 2 + 1] + bep[cl + 1], 0.f);
                    *(float2*)(gp + cl) = make_float2(v0, v1);
                }
            }
        }
    } else {
        const int f = fe >> 2;
        const float* bep = be + (size_t)fe * Uu + n0;
        const bool atom = (f < 2);   // discrete fields may overlap -> atomic
#pragma unroll
        for (int mi = 0; mi < 4; mi++) {
#pragma unroll
            for (int h = 0; h < 2; h++) {
                int rl = wm + mi * 16 + (lane >> 2) + h * 8;
                if (t0 + rl >= cnt) continue;
                int grow = sidx[rl];
                float* gp = g_field + (size_t)grow * (Ff * Uu) + (size_t)f * Uu + n0;
#pragma unroll
                for (int ni = 0; ni < 8; ni++) {
                    int cl = wn + ni * 8 + (lane & 3) * 2;
                    float v0 = fmaxf(acc[mi][ni][h * 2 + 0] + bep[cl],     0.f);
                    float v1 = fmaxf(acc[mi][ni][h * 2 + 1] + bep[cl + 1], 0.f);
                    if (atom) {
                        atomicAdd(gp + cl,     v0);
                        atomicAdd(gp + cl + 1, v1);
                    } else {
                        *(float2*)(gp + cl) = make_float2(v0, v1);
                    }
                }
            }
        }
    }
}

// ============================================================
// fused per-row epilogue: att/upd dots + softmax + mix (no x, no Wg)
// ============================================================
__global__ __launch_bounds__(256) void epilogue_kernel(
    const float* __restrict__ Wa, const float* __restrict__ ba,
    const float* __restrict__ Wu, const float* __restrict__ bu,
    float* __restrict__ out)
{
    const int b = blockIdx.x;
    __shared__ float cs[Uu];
    __shared__ float fs[Ff][Uu];
    __shared__ float s_att[Ff], s_upd[Ff];
    __shared__ float s_gates[Tt][Gg];

    const int tid = threadIdx.x;
    for (int i = tid; i < Uu; i += 256)
        cs[i] = g_common[(size_t)b * Uu + i];
    for (int i = tid; i < Ff * Uu; i += 256)
        fs[0][i] = g_field[(size_t)b * Ff * Uu + i];
    __syncthreads();

    const int w = tid >> 5, lane = tid & 31;

    // att/upd dots: warp w -> (f = w>>1, a/u = w&1)
    {
        int f = w >> 1;
        const float* Wv = (w & 1) ? (Wu + (size_t)f * 2 * Uu) : (Wa + (size_t)f * 2 * Uu);
        float s = 0.f;
        for (int k = lane; k < Uu; k += 32) s = fmaf(cs[k],    Wv[k],      s);
        for (int k = lane; k < Uu; k += 32) s = fmaf(fs[f][k], Wv[Uu + k], s);
#pragma unroll
        for (int o = 16; o; o >>= 1) s += __shfl_xor_sync(0xffffffffu, s, o);
        if (lane == 0) {
            float bv = (w & 1) ? bu[f] : ba[f];
            float v = 1.f / (1.f + expf(-(s + bv)));
            if (w & 1) s_upd[f] = v; else s_att[f] = v;
        }
    }
    __syncthreads();

    // softmax over F+1 experts per task (logits precomputed)
    if (tid < Tt) {
        const float* lg = g_logits + (size_t)b * (Tt * Gg) + tid * Gg;
        float mx = lg[0];
#pragma unroll
        for (int g = 1; g < Gg; g++) mx = fmaxf(mx, lg[g]);
        float ex[Gg], sum = 0.f;
#pragma unroll
        for (int g = 0; g < Gg; g++) { ex[g] = expf(lg[g] - mx); sum += ex[g]; }
        float inv = 1.f / sum;
#pragma unroll
        for (int g = 0; g < Gg; g++) s_gates[tid][g] = ex[g] * inv;
    }
    __syncthreads();

    for (int u = tid; u < Uu; u += 256) {
        float c = cs[u];
        float ffv[Ff];
#pragma unroll
        for (int f = 0; f < Ff; f++) {
            float fo = fs[f][u];
            float fa = s_att[f] * fo;
            ffv[f] = s_upd[f] * fa + (1.f - s_upd[f]) * c;
        }
#pragma unroll
        for (int t = 0; t < Tt; t++) {
            float o = s_gates[t][0] * c;
#pragma unroll
            for (int fq = 0; fq < Ff; fq++) o = fmaf(s_gates[t][1 + fq], ffv[fq], o);
            out[((size_t)b * Tt + t) * Uu + u] = o;
        }
    }
}

// ============================================================
// launch
// ============================================================
extern "C" void kernel_launch(void* const* d_in, const int* in_sizes, int n_in,
                              void* d_out, int out_size)
{
    const float* x  = (const float*)d_in[0];
    const float* Wc = (const float*)d_in[1];
    const float* bc = (const float*)d_in[2];
    const float* We = (const float*)d_in[3];
    const float* be = (const float*)d_in[4];
    const float* Wg = (const float*)d_in[5];
    const float* bg = (const float*)d_in[6];
    const float* Wa = (const float*)d_in[7];
    const float* ba = (const float*)d_in[8];
    const float* Wu = (const float*)d_in[9];
    const float* bu = (const float*)d_in[10];
    float* out = (float*)d_out;

    cudaFuncSetAttribute(gemm_all, cudaFuncAttributeMaxDynamicSharedMemorySize, DSM_TOTAL);

    zero_kernel<<<(Bsz * 2 * Uu / 4) / 256, 256>>>();
    build_idx<<<Bsz / 256, 256>>>(x);
    splitx_kernel<<<(Bsz * Dd / 4) / 256, 256>>>(x);
    splitw_kernel<<<dim3(Uu / 32, Dd / 32, NEXP), dim3(32, 8)>>>(Wc, We);
    glogits_kernel<<<Bsz / 8, 256>>>(x, Wg, bg);
    gemm_all<<<dim3(Bsz / BM, Uu / BN, 1 + Ff * Ee), 256, DSM_TOTAL>>>(bc, be);
    epilogue_kernel<<<Bsz, 256>>>(Wa, ba, Wu, bu, out);
}